// round 10
// baseline (speedup 1.0000x reference)
#include <cuda_runtime.h>

#define NT 256
#define BT 4

typedef unsigned long long u64;

// ---------------- packed f32x2 helpers ----------------
__device__ __forceinline__ void ffma2(u64 &acc, u64 a, u64 w) {
    asm("fma.rn.f32x2 %0, %1, %2, %0;" : "+l"(acc) : "l"(a), "l"(w));
}
__device__ __forceinline__ float sum2(u64 v) {
    return __uint_as_float((unsigned int)v) + __uint_as_float((unsigned int)(v >> 32));
}

// ---------------- activations ----------------
__device__ __forceinline__ float softplus_f(float x) {
    float r = __logf(1.f + __expf(x));
    return (x > 15.f) ? x : r;
}
__device__ __forceinline__ float tanh_f(float x) {
    float xx = fminf(fmaxf(x, -12.f), 12.f);
    float e = __expf(2.f * xx);
    return (e - 1.f) * __fdividef(1.f, e + 1.f);
}

// ---------------- k-major quad-interleaved weight layouts ----------------
// dst[(k>>2)*C*4 + c*4 + (k&3)] = src[c*K + k]
__device__ float g_vw3q[512 * 128];
__device__ float g_vw1k[128 * 64];
__device__ float g_vw2k[128 * 128];
__device__ float g_iw1k[128 * 8];
__device__ float g_iw2k[128 * 128];
__device__ float g_iw3k[64 * 128];

__device__ __forceinline__ void prep_one(float* dst, const float* src, int K, int id) {
    int c = id / K, k = id % K;
    int C4 = 0; // unused
    (void)C4;
    dst[(k >> 2) * (id / K >= 0 ? 0 : 0)] = 0.f; // placeholder avoided below
}

__global__ void prep_all(const float* __restrict__ vw3, const float* __restrict__ vw1,
                         const float* __restrict__ vw2, const float* __restrict__ iw1,
                         const float* __restrict__ iw2, const float* __restrict__ iw3) {
    int id = blockIdx.x * blockDim.x + threadIdx.x;
    if (id < 65536) {                              // vw3: C=512,K=128
        int c = id / 128, k = id % 128;
        g_vw3q[(k >> 2) * 2048 + c * 4 + (k & 3)] = vw3[id];
        return;
    }
    id -= 65536;
    if (id < 8192) {                               // vw1: C=128,K=64
        int c = id / 64, k = id % 64;
        g_vw1k[(k >> 2) * 512 + c * 4 + (k & 3)] = vw1[id];
        return;
    }
    id -= 8192;
    if (id < 16384) {                              // vw2: C=128,K=128
        int c = id / 128, k = id % 128;
        g_vw2k[(k >> 2) * 512 + c * 4 + (k & 3)] = vw2[id];
        return;
    }
    id -= 16384;
    if (id < 1024) {                               // iw1: C=128,K=8
        int c = id / 8, k = id % 8;
        g_iw1k[(k >> 2) * 512 + c * 4 + (k & 3)] = iw1[id];
        return;
    }
    id -= 1024;
    if (id < 16384) {                              // iw2: C=128,K=128
        int c = id / 128, k = id % 128;
        g_iw2k[(k >> 2) * 512 + c * 4 + (k & 3)] = iw2[id];
        return;
    }
    id -= 16384;
    if (id < 8192) {                               // iw3: C=64,K=128
        int c = id / 128, k = id % 128;
        g_iw3k[(k >> 2) * 256 + c * 4 + (k & 3)] = iw3[id];
        return;
    }
}

// ---------------- smem layout (floats), per CTA ----------------
#define OFF_W3C 0          // vw3 cols 384..511: 32 kq x 128 x 4 = 16384
#define OFF_B1  16384      // 128
#define OFF_B2  16512      // 128
#define OFF_B3  16640      // 512
#define OFF_LW  17152      // 64
#define OFF_DX  17216      // 32
#define OFF_Y   17280      // 4 x 64
#define OFF_YT  17536      // 4 x 64
#define OFF_H1  17792      // 4 x 128
#define OFF_H2  18304      // 4 x 128
#define OFF_K   18816      // 6 x 256
#define OFF_SC  20352      // scratch 4096
#define SMEM_FLOATS 24448
#define SMEM_BYTES (SMEM_FLOATS * 4)

enum { ACT_ID = 0, ACT_RELU = 1, ACT_SP = 2 };

// Generic split-K dense with gmem k-major weights (init path only).
// Halves of 128 threads. OUT[4][C] = act(ACTS[4][K] @ W^T + bias).
template<int C, int K, int AS, int ACT>
__device__ __forceinline__ void dense_g(const float* __restrict__ wk,
                                        const float* __restrict__ bias,
                                        const float* __restrict__ act,
                                        float* __restrict__ scratch,
                                        float* __restrict__ outp, int tid) {
    const int half = tid >> 7;
    const int t2 = tid & 127;
    constexpr int G = 128 / C;          // 1 (C=128) or 2 (C=64)
    constexpr int RPT = 4 / G;
    constexpr int KQH = (K / 4) / 2;    // k-quads per half
    const int c  = t2 % C;
    const int r0 = (t2 / C) * RPT;

    u64 acc[RPT][2];
#pragma unroll
    for (int i = 0; i < RPT; i++) { acc[i][0] = 0ull; acc[i][1] = 0ull; }

#pragma unroll
    for (int q = 0; q < KQH; q++) {
        const int kq = half * KQH + q;
        ulonglong2 w = *(const ulonglong2*)(wk + kq * C * 4 + c * 4);
#pragma unroll
        for (int i = 0; i < RPT; i++) {
            ulonglong2 a = *(const ulonglong2*)(act + (r0 + i) * AS + kq * 4);
            ffma2(acc[i][0], a.x, w.x);
            ffma2(acc[i][1], a.y, w.y);
        }
    }
#pragma unroll
    for (int i = 0; i < RPT; i++)
        scratch[half * (4 * C) + (r0 + i) * C + c] = sum2(acc[i][0]) + sum2(acc[i][1]);
    __syncthreads();

#pragma unroll
    for (int i = tid; i < 4 * C; i += NT) {
        float v = scratch[i] + scratch[4 * C + i] + bias[i % C];
        if (ACT == ACT_RELU) v = fmaxf(v, 0.f);
        if (ACT == ACT_SP)   v = softplus_f(v);
        outp[i] = v;
    }
}

// L1 recurrent: C=128, K=64, register weights (8 x ulonglong2 slice).
__device__ __forceinline__ void dense1_reg(const ulonglong2* __restrict__ w1r,
                                           const float* __restrict__ bias,
                                           const float* __restrict__ ysrc,
                                           float* __restrict__ scratch,
                                           float* __restrict__ outp, int tid) {
    const int half = tid >> 7;
    const int c = tid & 127;
    u64 acc[4][2];
#pragma unroll
    for (int i = 0; i < 4; i++) { acc[i][0] = 0ull; acc[i][1] = 0ull; }
#pragma unroll
    for (int q = 0; q < 8; q++) {
        ulonglong2 w = w1r[q];
        const int k4 = (half * 8 + q) * 4;
#pragma unroll
        for (int i = 0; i < 4; i++) {
            ulonglong2 a = *(const ulonglong2*)(ysrc + i * 64 + k4);
            ffma2(acc[i][0], a.x, w.x);
            ffma2(acc[i][1], a.y, w.y);
        }
    }
#pragma unroll
    for (int i = 0; i < 4; i++)
        scratch[half * 512 + i * 128 + c] = sum2(acc[i][0]) + sum2(acc[i][1]);
    __syncthreads();
#pragma unroll
    for (int i = tid; i < 512; i += NT)
        outp[i] = softplus_f(scratch[i] + scratch[512 + i] + bias[i & 127]);
}

// L2 recurrent: C=128, K=128, register weights (16 x ulonglong2 slice).
__device__ __forceinline__ void dense2_reg(const ulonglong2* __restrict__ w2r,
                                           const float* __restrict__ bias,
                                           const float* __restrict__ h1,
                                           float* __restrict__ scratch,
                                           float* __restrict__ outp, int tid) {
    const int half = tid >> 7;
    const int c = tid & 127;
    u64 acc[4][2];
#pragma unroll
    for (int i = 0; i < 4; i++) { acc[i][0] = 0ull; acc[i][1] = 0ull; }
#pragma unroll
    for (int q = 0; q < 16; q++) {
        ulonglong2 w = w2r[q];
        const int k4 = (half * 16 + q) * 4;
#pragma unroll
        for (int i = 0; i < 4; i++) {
            ulonglong2 a = *(const ulonglong2*)(h1 + i * 128 + k4);
            ffma2(acc[i][0], a.x, w.x);
            ffma2(acc[i][1], a.y, w.y);
        }
    }
#pragma unroll
    for (int i = 0; i < 4; i++)
        scratch[half * 512 + i * 128 + c] = sum2(acc[i][0]) + sum2(acc[i][1]);
    __syncthreads();
#pragma unroll
    for (int i = tid; i < 512; i += NT)
        outp[i] = softplus_f(scratch[i] + scratch[512 + i] + bias[i & 127]);
}

// L3: 512 cols split-K; thread owns cols t2+128j (j=0..2 streamed, j=3 smem).
__device__ __forceinline__ void l3_sk(const float* __restrict__ h2s,
                                      const float* __restrict__ w3c,
                                      const float* __restrict__ b3s,
                                      const float* __restrict__ dxs,
                                      float* __restrict__ scratch,
                                      float* __restrict__ kout, int tid) {
    const int half = tid >> 7;
    const int t2 = tid & 127;

    u64 acc[4][4];   // [row][colgroup]
#pragma unroll
    for (int r = 0; r < 4; r++)
#pragma unroll
        for (int j = 0; j < 4; j++) acc[r][j] = 0ull;

    const float* gb = g_vw3q + (half * 16) * 2048 + t2 * 4;
    const float* cb = w3c + (half * 16) * 512 + t2 * 4;

#pragma unroll
    for (int q = 0; q < 16; q++) {
        ulonglong2 w0 = *(const ulonglong2*)(gb + q * 2048);
        ulonglong2 w1 = *(const ulonglong2*)(gb + q * 2048 + 512);
        ulonglong2 w2 = *(const ulonglong2*)(gb + q * 2048 + 1024);
        ulonglong2 w3 = *(const ulonglong2*)(cb + q * 512);
        const int k4 = (half * 16 + q) * 4;
#pragma unroll
        for (int r = 0; r < 4; r++) {
            ulonglong2 a = *(const ulonglong2*)(h2s + r * 128 + k4);
            ffma2(acc[r][0], a.x, w0.x); ffma2(acc[r][0], a.y, w0.y);
            ffma2(acc[r][1], a.x, w1.x); ffma2(acc[r][1], a.y, w1.y);
            ffma2(acc[r][2], a.x, w2.x); ffma2(acc[r][2], a.y, w2.y);
            ffma2(acc[r][3], a.x, w3.x); ffma2(acc[r][3], a.y, w3.y);
        }
    }
#pragma unroll
    for (int r = 0; r < 4; r++)
#pragma unroll
        for (int j = 0; j < 4; j++)
            scratch[half * 2048 + r * 512 + t2 + 128 * j] = sum2(acc[r][j]);
    __syncthreads();

    const int d  = tid & 7;
#pragma unroll
    for (int cc = 0; cc < 2; cc++) {
        const int c = tid + cc * 256;
        const int h0 = c >> 3;
        const float b3v = b3s[c];
#pragma unroll
        for (int r = 0; r < 4; r++) {
            float v = scratch[r * 512 + c] + scratch[2048 + r * 512 + c] + b3v;
            float f = tanh_f(v) * dxs[r * 8 + d];
            f += __shfl_xor_sync(0xffffffffu, f, 1);
            f += __shfl_xor_sync(0xffffffffu, f, 2);
            f += __shfl_xor_sync(0xffffffffu, f, 4);
            if (d == 0) kout[r * 64 + h0] = f;
        }
    }
}

__device__ __forceinline__ void vf(const float* __restrict__ ysrc, float* __restrict__ kout,
                                   const ulonglong2* w1r, const float* b1s,
                                   const ulonglong2* w2r, const float* b2s,
                                   const float* w3c, const float* b3s,
                                   const float* dxs,
                                   float* scratch, float* h1, float* h2, int tid) {
    dense1_reg(w1r, b1s, ysrc, scratch, h1, tid);
    __syncthreads();
    dense2_reg(w2r, b2s, h1, scratch, h2, tid);
    __syncthreads();
    l3_sk(h2, w3c, b3s, dxs, scratch, kout, tid);
    __syncthreads();
}

__device__ __forceinline__ void write_out(const float* __restrict__ y,
                                          const float* __restrict__ lws, float lbv,
                                          float* __restrict__ out, int b0, int t, int tid) {
    int w = tid >> 5, l = tid & 31;
    if (w < BT) {
        float p = y[w * 64 + l] * lws[l] + y[w * 64 + 32 + l] * lws[32 + l];
#pragma unroll
        for (int s = 16; s > 0; s >>= 1) p += __shfl_xor_sync(0xffffffffu, p, s);
        if (l == 0) {
            float z = p + lbv;
            out[(b0 + w) * 64 + t] = __fdividef(1.f, 1.f + __expf(-z));
        }
    }
}

__global__ void __launch_bounds__(NT, 2)
cde_kernel(const float* __restrict__ ts, const float* __restrict__ xs,
           const float* __restrict__ ib1, const float* __restrict__ ib2,
           const float* __restrict__ ib3,
           const float* __restrict__ vb1, const float* __restrict__ vb2,
           const float* __restrict__ vb3,
           const float* __restrict__ lw, const float* __restrict__ lb,
           float* __restrict__ out) {
    extern __shared__ float sm[];
    const int tid = threadIdx.x;
    const int b0 = blockIdx.x * BT;

    float* w3c = sm + OFF_W3C;
    float* b1s = sm + OFF_B1;
    float* b2s = sm + OFF_B2;
    float* b3s = sm + OFF_B3;
    float* lws = sm + OFF_LW;
    float* dxs = sm + OFF_DX;
    float* ybuf = sm + OFF_Y;
    float* yts = sm + OFF_YT;
    float* h1 = sm + OFF_H1;
    float* h2 = sm + OFF_H2;
    float* ksb = sm + OFF_K;
    float* scratch = sm + OFF_SC;

    // ---------- stage smem ----------
    // vw3 cols 384..511 cache: w3c[kq*512 + j] = g_vw3q[kq*2048 + 1536 + j]
    for (int i = tid; i < 16384; i += NT)
        w3c[i] = g_vw3q[(i >> 9) * 2048 + 1536 + (i & 511)];
    for (int i = tid; i < 128; i += NT) { b1s[i] = vb1[i]; b2s[i] = vb2[i]; }
    for (int i = tid; i < 512; i += NT) b3s[i] = vb3[i];
    if (tid < 64) lws[tid] = lw[tid];
    if (tid < 32) {
        int r = tid >> 3, d = tid & 7;
        dxs[tid] = xs[(b0 + r) * 512 + d];        // X(t0)
    }
    const float lbv = lb[0];

    // ---------- register-resident vw1 / vw2 slices ----------
    ulonglong2 w1r[8], w2r[16];
    {
        const int half = tid >> 7;
        const int c = tid & 127;
#pragma unroll
        for (int q = 0; q < 8; q++)
            w1r[q] = *(const ulonglong2*)(g_vw1k + (half * 8 + q) * 512 + c * 4);
#pragma unroll
        for (int q = 0; q < 16; q++)
            w2r[q] = *(const ulonglong2*)(g_vw2k + (half * 16 + q) * 512 + c * 4);
    }
    __syncthreads();

    // ---------- initial MLP ----------
    dense_g<128, 8, 8, ACT_RELU>(g_iw1k, ib1, dxs, scratch, h1, tid);
    __syncthreads();
    dense_g<128, 128, 128, ACT_RELU>(g_iw2k, ib2, h1, scratch, h2, tid);
    __syncthreads();
    dense_g<64, 128, 128, ACT_ID>(g_iw3k, ib3, h2, scratch, ybuf, tid);
    __syncthreads();

    write_out(ybuf, lws, lbv, out, b0, 0, tid);
    __syncthreads();

    // Tsit5 coefficients
    const float A21 = 0.161f;
    const float A31 = -0.008480655492356989f, A32 = 0.335480655492357f;
    const float A41 = 2.8971530571054935f, A42 = -6.359448489975075f, A43 = 4.3622954328695815f;
    const float A51 = 5.325864828439257f, A52 = -11.748883564062828f, A53 = 7.4955393428898365f, A54 = -0.09249506636175525f;
    const float A61 = 5.86145544294642f, A62 = -12.92096931784711f, A63 = 8.159367898576159f, A64 = -0.071584973281401f, A65 = -0.028269050394068383f;
    const float B1 = 0.09646076681806523f, B2 = 0.01f, B3 = 0.4798896504144996f;
    const float B4 = 1.379008574103742f, B5 = -3.290069515436081f, B6 = 2.324710524099774f;

    float* k1 = ksb;
    float* k2 = ksb + 256;
    float* k3 = ksb + 512;
    float* k4 = ksb + 768;
    float* k5 = ksb + 1024;
    float* k6 = ksb + 1280;

    for (int t = 0; t < 63; t++) {
        const float dt = ts[t + 1] - ts[t];
        if (tid < 32) {
            int r = tid >> 3, d = tid & 7;
            int ix = (b0 + r) * 512 + t * 8 + d;
            dxs[tid] = (xs[ix + 8] - xs[ix]) / dt;
        }
        __syncthreads();

        vf(ybuf, k1, w1r, b1s, w2r, b2s, w3c, b3s, dxs, scratch, h1, h2, tid);
        yts[tid] = ybuf[tid] + dt * (A21 * k1[tid]);
        __syncthreads();

        vf(yts, k2, w1r, b1s, w2r, b2s, w3c, b3s, dxs, scratch, h1, h2, tid);
        yts[tid] = ybuf[tid] + dt * (A31 * k1[tid] + A32 * k2[tid]);
        __syncthreads();

        vf(yts, k3, w1r, b1s, w2r, b2s, w3c, b3s, dxs, scratch, h1, h2, tid);
        yts[tid] = ybuf[tid] + dt * (A41 * k1[tid] + A42 * k2[tid] + A43 * k3[tid]);
        __syncthreads();

        vf(yts, k4, w1r, b1s, w2r, b2s, w3c, b3s, dxs, scratch, h1, h2, tid);
        yts[tid] = ybuf[tid] + dt * (A51 * k1[tid] + A52 * k2[tid] + A53 * k3[tid] + A54 * k4[tid]);
        __syncthreads();

        vf(yts, k5, w1r, b1s, w2r, b2s, w3c, b3s, dxs, scratch, h1, h2, tid);
        yts[tid] = ybuf[tid] + dt * (A61 * k1[tid] + A62 * k2[tid] + A63 * k3[tid] + A64 * k4[tid] + A65 * k5[tid]);
        __syncthreads();

        vf(yts, k6, w1r, b1s, w2r, b2s, w3c, b3s, dxs, scratch, h1, h2, tid);
        ybuf[tid] = ybuf[tid] + dt * (B1 * k1[tid] + B2 * k2[tid] + B3 * k3[tid]
                                    + B4 * k4[tid] + B5 * k5[tid] + B6 * k6[tid]);
        __syncthreads();

        write_out(ybuf, lws, lbv, out, b0, t + 1, tid);
        __syncthreads();
    }
}

extern "C" void kernel_launch(void* const* d_in, const int* in_sizes, int n_in,
                              void* d_out, int out_size) {
    const float* ts  = (const float*)d_in[0];
    const float* xs  = (const float*)d_in[1];
    const float* iw1 = (const float*)d_in[2];
    const float* ib1 = (const float*)d_in[3];
    const float* iw2 = (const float*)d_in[4];
    const float* ib2 = (const float*)d_in[5];
    const float* iw3 = (const float*)d_in[6];
    const float* ib3 = (const float*)d_in[7];
    const float* vw1 = (const float*)d_in[8];
    const float* vb1 = (const float*)d_in[9];
    const float* vw2 = (const float*)d_in[10];
    const float* vb2 = (const float*)d_in[11];
    const float* vw3 = (const float*)d_in[12];
    const float* vb3 = (const float*)d_in[13];
    const float* lw  = (const float*)d_in[14];
    const float* lb  = (const float*)d_in[15];
    float* out = (float*)d_out;

    prep_all<<<(115712 + 255) / 256, 256>>>(vw3, vw1, vw2, iw1, iw2, iw3);

    cudaFuncSetAttribute(cde_kernel, cudaFuncAttributeMaxDynamicSharedMemorySize, SMEM_BYTES);
    cde_kernel<<<256, NT, SMEM_BYTES>>>(ts, xs, ib1, ib2, ib3,
                                        vb1, vb2, vb3, lw, lb, out);
}

// round 12
// speedup vs baseline: 1.3709x; 1.3709x over previous
#include <cuda_runtime.h>

#define NT 512
#define BT 8

typedef unsigned long long u64;

// ---------------- packed f32x2 helpers ----------------
__device__ __forceinline__ void ffma2(u64 &acc, u64 a, u64 w) {
    asm("fma.rn.f32x2 %0, %1, %2, %0;" : "+l"(acc) : "l"(a), "l"(w));
}
__device__ __forceinline__ float sum2(u64 v) {
    return __uint_as_float((unsigned int)v) + __uint_as_float((unsigned int)(v >> 32));
}

// ---------------- activations ----------------
__device__ __forceinline__ float softplus_f(float x) {
    float r = __logf(1.f + __expf(x));
    return (x > 15.f) ? x : r;
}
__device__ __forceinline__ float tanh_f(float x) {
    float xx = fminf(fmaxf(x, -12.f), 12.f);
    float e = __expf(2.f * xx);
    return (e - 1.f) * __fdividef(1.f, e + 1.f);
}

// ---------------- k-major quad-interleaved weight layouts ----------------
// dst[(k>>2)*C*4 + c*4 + (k&3)] = src[c*K + k]
__device__ float g_vw3q[512 * 128];
__device__ float g_vw1k[128 * 64];
__device__ float g_vw2k[128 * 128];
__device__ float g_iw1k[128 * 8];
__device__ float g_iw2k[128 * 128];
__device__ float g_iw3k[64 * 128];

__global__ void prep_all(const float* __restrict__ vw3, const float* __restrict__ vw1,
                         const float* __restrict__ vw2, const float* __restrict__ iw1,
                         const float* __restrict__ iw2, const float* __restrict__ iw3) {
    int id = blockIdx.x * blockDim.x + threadIdx.x;
    if (id < 65536) {                              // vw3: C=512,K=128
        int c = id / 128, k = id % 128;
        g_vw3q[(k >> 2) * 2048 + c * 4 + (k & 3)] = vw3[id];
        return;
    }
    id -= 65536;
    if (id < 8192) {                               // vw1: C=128,K=64
        int c = id / 64, k = id % 64;
        g_vw1k[(k >> 2) * 512 + c * 4 + (k & 3)] = vw1[id];
        return;
    }
    id -= 8192;
    if (id < 16384) {                              // vw2: C=128,K=128
        int c = id / 128, k = id % 128;
        g_vw2k[(k >> 2) * 512 + c * 4 + (k & 3)] = vw2[id];
        return;
    }
    id -= 16384;
    if (id < 1024) {                               // iw1: C=128,K=8
        int c = id / 8, k = id % 8;
        g_iw1k[(k >> 2) * 512 + c * 4 + (k & 3)] = iw1[id];
        return;
    }
    id -= 1024;
    if (id < 16384) {                              // iw2: C=128,K=128
        int c = id / 128, k = id % 128;
        g_iw2k[(k >> 2) * 512 + c * 4 + (k & 3)] = iw2[id];
        return;
    }
    id -= 16384;
    if (id < 8192) {                               // iw3: C=64,K=128
        int c = id / 128, k = id % 128;
        g_iw3k[(k >> 2) * 256 + c * 4 + (k & 3)] = iw3[id];
        return;
    }
}

// ---------------- smem layout (floats) ----------------
#define OFF_W3C 0          // vw3 cols 256..511: 32 kq x 256 x 4 = 32768
#define OFF_B1  32768      // 128
#define OFF_B2  32896      // 128
#define OFF_B3  33024      // 512
#define OFF_LW  33536      // 64
#define OFF_DX  33600      // 64
#define OFF_Y   33664      // 512
#define OFF_YT  34176      // 512
#define OFF_H1  34688      // 8 x 128
#define OFF_H2  35712      // 8 x 128
#define OFF_K   36736      // 6 x 512
#define OFF_SC  39808      // scratch 8192 (4 planes dense / 2 planes l3)
#define SMEM_FLOATS 48000
#define SMEM_BYTES (SMEM_FLOATS * 4)

enum { ACT_ID = 0, ACT_RELU = 1, ACT_SP = 2 };

// Generic split-K (S=2) dense for init path only; gmem k-major weights.
template<int C, int K, int ACT>
__device__ __forceinline__ void dense_sk(const float* __restrict__ wk,
                                         const float* __restrict__ bias,
                                         const float* __restrict__ actbuf,
                                         float* __restrict__ scratch,
                                         float* __restrict__ outp, int tid) {
    const int half = tid >> 8;
    const int t2 = tid & 255;
    constexpr int G = 256 / C;
    constexpr int RPT = 8 / G;
    constexpr int KQH = K / 8;
    const int c  = t2 % C;
    const int r0 = (t2 / C) * RPT;
    const int kq0 = half * KQH;

    u64 acc[RPT][2];
#pragma unroll
    for (int i = 0; i < RPT; i++) { acc[i][0] = 0ull; acc[i][1] = 0ull; }

#pragma unroll
    for (int q = 0; q < KQH; q++) {
        const int kq = kq0 + q;
        ulonglong2 w = *(const ulonglong2*)(wk + kq * C * 4 + c * 4);
#pragma unroll
        for (int i = 0; i < RPT; i++) {
            ulonglong2 a = *(const ulonglong2*)(actbuf + (r0 + i) * K + kq * 4);
            ffma2(acc[i][0], a.x, w.x);
            ffma2(acc[i][1], a.y, w.y);
        }
    }
#pragma unroll
    for (int i = 0; i < RPT; i++)
        scratch[half * (8 * C) + (r0 + i) * C + c] = sum2(acc[i][0]) + sum2(acc[i][1]);
    __syncthreads();

#pragma unroll
    for (int i = tid; i < 8 * C; i += NT) {
        float v = scratch[i] + scratch[8 * C + i] + bias[i % C];
        if (ACT == ACT_RELU) v = fmaxf(v, 0.f);
        if (ACT == ACT_SP)   v = softplus_f(v);
        outp[i] = v;
    }
}

// L1 recurrent: C=128, K=64, S=4 k-split, register weights (4 u64 quads).
// thread = (g = tid>>7, c = tid&127); owns all 8 rows, k-range [g*16, g*16+16).
__device__ __forceinline__ void dense1_reg(const ulonglong2* __restrict__ w1r,
                                           const float* __restrict__ bias,
                                           const float* __restrict__ ysrc,
                                           float* __restrict__ scratch,
                                           float* __restrict__ outp, int tid) {
    const int g = tid >> 7;
    const int c = tid & 127;
    u64 acc[8];
#pragma unroll
    for (int r = 0; r < 8; r++) acc[r] = 0ull;
#pragma unroll
    for (int q = 0; q < 4; q++) {
        ulonglong2 w = w1r[q];
        const int k4 = (g * 4 + q) * 4;
#pragma unroll
        for (int r = 0; r < 8; r++) {
            ulonglong2 a = *(const ulonglong2*)(ysrc + r * 64 + k4);
            ffma2(acc[r], a.x, w.x);
            ffma2(acc[r], a.y, w.y);
        }
    }
#pragma unroll
    for (int r = 0; r < 8; r++)
        scratch[g * 1024 + r * 128 + c] = sum2(acc[r]);
    __syncthreads();
#pragma unroll
    for (int i = tid; i < 1024; i += NT) {
        float v = scratch[i] + scratch[1024 + i] + scratch[2048 + i] + scratch[3072 + i]
                + bias[i & 127];
        outp[i] = softplus_f(v);
    }
}

// L2 recurrent: C=128, K=128, S=4 k-split, register weights (8 u64 quads).
__device__ __forceinline__ void dense2_reg(const ulonglong2* __restrict__ w2r,
                                           const float* __restrict__ bias,
                                           const float* __restrict__ h1,
                                           float* __restrict__ scratch,
                                           float* __restrict__ outp, int tid) {
    const int g = tid >> 7;
    const int c = tid & 127;
    u64 acc[8];
#pragma unroll
    for (int r = 0; r < 8; r++) acc[r] = 0ull;
#pragma unroll
    for (int q = 0; q < 8; q++) {
        ulonglong2 w = w2r[q];
        const int k4 = (g * 8 + q) * 4;
#pragma unroll
        for (int r = 0; r < 8; r++) {
            ulonglong2 a = *(const ulonglong2*)(h1 + r * 128 + k4);
            ffma2(acc[r], a.x, w.x);
            ffma2(acc[r], a.y, w.y);
        }
    }
#pragma unroll
    for (int r = 0; r < 8; r++)
        scratch[g * 1024 + r * 128 + c] = sum2(acc[r]);
    __syncthreads();
#pragma unroll
    for (int i = tid; i < 1024; i += NT) {
        float v = scratch[i] + scratch[1024 + i] + scratch[2048 + i] + scratch[3072 + i]
                + bias[i & 127];
        outp[i] = softplus_f(v);
    }
}

// L3 (512 cols, K=128) split-K (S=2) + tanh + dx-contraction -> kout[8][64].
// Col t2 streamed from L2 (depth-2 prefetch), col t2+256 from SMEM cache.
__device__ __forceinline__ void l3_sk(const float* __restrict__ h2s,
                                      const float* __restrict__ w3c,
                                      const float* __restrict__ b3s,
                                      const float* __restrict__ dxs,
                                      float* __restrict__ scratch,
                                      float* __restrict__ kout, int tid) {
    const int half = tid >> 8;
    const int t2 = tid & 255;

    u64 acc0[8], acc1[8];
#pragma unroll
    for (int r = 0; r < 8; r++) { acc0[r] = 0ull; acc1[r] = 0ull; }

    const float* gb = g_vw3q + (half * 16) * 2048 + t2 * 4;
    const float* cb = w3c + (half * 16) * 1024 + t2 * 4;
    ulonglong2 p0 = *(const ulonglong2*)(gb);
    ulonglong2 p1 = *(const ulonglong2*)(gb + 2048);

#pragma unroll
    for (int q = 0; q < 16; q++) {
        ulonglong2 w0 = p0;
        p0 = p1;
        if (q + 2 < 16) p1 = *(const ulonglong2*)(gb + (q + 2) * 2048);
        ulonglong2 w1 = *(const ulonglong2*)(cb + q * 1024);
        const int k4 = (half * 16 + q) * 4;
#pragma unroll
        for (int r = 0; r < 8; r++) {
            ulonglong2 a = *(const ulonglong2*)(h2s + r * 128 + k4);
            ffma2(acc0[r], a.x, w0.x);
            ffma2(acc0[r], a.y, w0.y);
            ffma2(acc1[r], a.x, w1.x);
            ffma2(acc1[r], a.y, w1.y);
        }
    }
#pragma unroll
    for (int r = 0; r < 8; r++) {
        scratch[half * 4096 + r * 512 + t2]       = sum2(acc0[r]);
        scratch[half * 4096 + r * 512 + t2 + 256] = sum2(acc1[r]);
    }
    __syncthreads();

    const int d  = tid & 7;
    const int h0 = tid >> 3;
    const float b3v = b3s[tid];
#pragma unroll
    for (int r = 0; r < 8; r++) {
        float v = scratch[r * 512 + tid] + scratch[4096 + r * 512 + tid] + b3v;
        float f = tanh_f(v) * dxs[r * 8 + d];
        f += __shfl_xor_sync(0xffffffffu, f, 1);
        f += __shfl_xor_sync(0xffffffffu, f, 2);
        f += __shfl_xor_sync(0xffffffffu, f, 4);
        if (d == 0) kout[r * 64 + h0] = f;
    }
}

__device__ __forceinline__ void vf(const float* __restrict__ ysrc, float* __restrict__ kout,
                                   const ulonglong2* w1r, const float* b1s,
                                   const ulonglong2* w2r, const float* b2s,
                                   const float* w3c, const float* b3s,
                                   const float* dxs,
                                   float* scratch, float* h1, float* h2, int tid) {
    dense1_reg(w1r, b1s, ysrc, scratch, h1, tid);
    __syncthreads();
    dense2_reg(w2r, b2s, h1, scratch, h2, tid);
    __syncthreads();
    l3_sk(h2, w3c, b3s, dxs, scratch, kout, tid);
    __syncthreads();
}

__device__ __forceinline__ void write_out(const float* __restrict__ y,
                                          const float* __restrict__ lws, float lbv,
                                          float* __restrict__ out, int b0, int t, int tid) {
    int w = tid >> 5, l = tid & 31;
    if (w < 8) {
        float p = y[w * 64 + l] * lws[l] + y[w * 64 + 32 + l] * lws[32 + l];
#pragma unroll
        for (int s = 16; s > 0; s >>= 1) p += __shfl_xor_sync(0xffffffffu, p, s);
        if (l == 0) {
            float z = p + lbv;
            out[(b0 + w) * 64 + t] = __fdividef(1.f, 1.f + __expf(-z));
        }
    }
}

__global__ void __launch_bounds__(NT, 1)
cde_kernel(const float* __restrict__ ts, const float* __restrict__ xs,
           const float* __restrict__ ib1, const float* __restrict__ ib2,
           const float* __restrict__ ib3,
           const float* __restrict__ vb1, const float* __restrict__ vb2,
           const float* __restrict__ vb3,
           const float* __restrict__ lw, const float* __restrict__ lb,
           float* __restrict__ out) {
    extern __shared__ float sm[];
    const int tid = threadIdx.x;
    const int b0 = blockIdx.x * BT;

    float* w3c = sm + OFF_W3C;
    float* b1s = sm + OFF_B1;
    float* b2s = sm + OFF_B2;
    float* b3s = sm + OFF_B3;
    float* lws = sm + OFF_LW;
    float* dxs = sm + OFF_DX;
    float* ybuf = sm + OFF_Y;
    float* yts = sm + OFF_YT;
    float* h1 = sm + OFF_H1;
    float* h2 = sm + OFF_H2;
    float* ksb = sm + OFF_K;
    float* scratch = sm + OFF_SC;

    // ---------- stage smem ----------
    // vw3 cols 256..511 cache: w3c[kq*1024 + j] = g_vw3q[kq*2048 + 1024 + j]
    for (int i = tid; i < 32768; i += NT)
        w3c[i] = g_vw3q[(i >> 10) * 2048 + 1024 + (i & 1023)];
    for (int i = tid; i < 128; i += NT) { b1s[i] = vb1[i]; b2s[i] = vb2[i]; }
    for (int i = tid; i < 512; i += NT) b3s[i] = vb3[i];
    if (tid < 64) lws[tid] = lw[tid];
    if (tid < 64) {
        int r = tid >> 3, d = tid & 7;
        dxs[tid] = xs[(b0 + r) * 512 + d];         // X(t0)
    }
    const float lbv = lb[0];

    // ---------- register-resident vw1/vw2 slices (S=4) ----------
    ulonglong2 w1r[4], w2r[8];
    {
        const int g = tid >> 7;
        const int c = tid & 127;
#pragma unroll
        for (int q = 0; q < 4; q++)
            w1r[q] = *(const ulonglong2*)(g_vw1k + (g * 4 + q) * 512 + c * 4);
#pragma unroll
        for (int q = 0; q < 8; q++)
            w2r[q] = *(const ulonglong2*)(g_vw2k + (g * 8 + q) * 512 + c * 4);
    }
    __syncthreads();

    // ---------- initial MLP (gmem k-major weights, S=2 generic) ----------
    dense_sk<128, 8, ACT_RELU>(g_iw1k, ib1, dxs, scratch, h1, tid);
    __syncthreads();
    dense_sk<128, 128, ACT_RELU>(g_iw2k, ib2, h1, scratch, h2, tid);
    __syncthreads();
    dense_sk<64, 128, ACT_ID>(g_iw3k, ib3, h2, scratch, ybuf, tid);
    __syncthreads();

    write_out(ybuf, lws, lbv, out, b0, 0, tid);
    __syncthreads();

    // Tsit5 coefficients
    const float A21 = 0.161f;
    const float A31 = -0.008480655492356989f, A32 = 0.335480655492357f;
    const float A41 = 2.8971530571054935f, A42 = -6.359448489975075f, A43 = 4.3622954328695815f;
    const float A51 = 5.325864828439257f, A52 = -11.748883564062828f, A53 = 7.4955393428898365f, A54 = -0.09249506636175525f;
    const float A61 = 5.86145544294642f, A62 = -12.92096931784711f, A63 = 8.159367898576159f, A64 = -0.071584973281401f, A65 = -0.028269050394068383f;
    const float B1 = 0.09646076681806523f, B2 = 0.01f, B3 = 0.4798896504144996f;
    const float B4 = 1.379008574103742f, B5 = -3.290069515436081f, B6 = 2.324710524099774f;

    float* k1 = ksb;
    float* k2 = ksb + 512;
    float* k3 = ksb + 1024;
    float* k4 = ksb + 1536;
    float* k5 = ksb + 2048;
    float* k6 = ksb + 2560;

    for (int t = 0; t < 63; t++) {
        const float dt = ts[t + 1] - ts[t];
        if (tid < 64) {
            int r = tid >> 3, d = tid & 7;
            int ix = (b0 + r) * 512 + t * 8 + d;
            dxs[tid] = (xs[ix + 8] - xs[ix]) / dt;
        }
        __syncthreads();

        vf(ybuf, k1, w1r, b1s, w2r, b2s, w3c, b3s, dxs, scratch, h1, h2, tid);
        yts[tid] = ybuf[tid] + dt * (A21 * k1[tid]);
        __syncthreads();

        vf(yts, k2, w1r, b1s, w2r, b2s, w3c, b3s, dxs, scratch, h1, h2, tid);
        yts[tid] = ybuf[tid] + dt * (A31 * k1[tid] + A32 * k2[tid]);
        __syncthreads();

        vf(yts, k3, w1r, b1s, w2r, b2s, w3c, b3s, dxs, scratch, h1, h2, tid);
        yts[tid] = ybuf[tid] + dt * (A41 * k1[tid] + A42 * k2[tid] + A43 * k3[tid]);
        __syncthreads();

        vf(yts, k4, w1r, b1s, w2r, b2s, w3c, b3s, dxs, scratch, h1, h2, tid);
        yts[tid] = ybuf[tid] + dt * (A51 * k1[tid] + A52 * k2[tid] + A53 * k3[tid] + A54 * k4[tid]);
        __syncthreads();

        vf(yts, k5, w1r, b1s, w2r, b2s, w3c, b3s, dxs, scratch, h1, h2, tid);
        yts[tid] = ybuf[tid] + dt * (A61 * k1[tid] + A62 * k2[tid] + A63 * k3[tid] + A64 * k4[tid] + A65 * k5[tid]);
        __syncthreads();

        vf(yts, k6, w1r, b1s, w2r, b2s, w3c, b3s, dxs, scratch, h1, h2, tid);
        ybuf[tid] = ybuf[tid] + dt * (B1 * k1[tid] + B2 * k2[tid] + B3 * k3[tid]
                                    + B4 * k4[tid] + B5 * k5[tid] + B6 * k6[tid]);
        __syncthreads();

        write_out(ybuf, lws, lbv, out, b0, t + 1, tid);
        __syncthreads();
    }
}

extern "C" void kernel_launch(void* const* d_in, const int* in_sizes, int n_in,
                              void* d_out, int out_size) {
    const float* ts  = (const float*)d_in[0];
    const float* xs  = (const float*)d_in[1];
    const float* iw1 = (const float*)d_in[2];
    const float* ib1 = (const float*)d_in[3];
    const float* iw2 = (const float*)d_in[4];
    const float* ib2 = (const float*)d_in[5];
    const float* iw3 = (const float*)d_in[6];
    const float* ib3 = (const float*)d_in[7];
    const float* vw1 = (const float*)d_in[8];
    const float* vb1 = (const float*)d_in[9];
    const float* vw2 = (const float*)d_in[10];
    const float* vb2 = (const float*)d_in[11];
    const float* vw3 = (const float*)d_in[12];
    const float* vb3 = (const float*)d_in[13];
    const float* lw  = (const float*)d_in[14];
    const float* lb  = (const float*)d_in[15];
    float* out = (float*)d_out;

    prep_all<<<(115712 + 255) / 256, 256>>>(vw3, vw1, vw2, iw1, iw2, iw3);

    cudaFuncSetAttribute(cde_kernel, cudaFuncAttributeMaxDynamicSharedMemorySize, SMEM_BYTES);
    cde_kernel<<<128, NT, SMEM_BYTES>>>(ts, xs, ib1, ib2, ib3,
                                        vb1, vb2, vb3, lw, lb, out);
}

// round 16
// speedup vs baseline: 1.4102x; 1.0286x over previous
#include <cuda_runtime.h>

#define NT 512
#define BT 8

typedef unsigned long long u64;

// ---------------- packed f32x2 helpers ----------------
__device__ __forceinline__ void ffma2(u64 &acc, u64 a, u64 w) {
    asm("fma.rn.f32x2 %0, %1, %2, %0;" : "+l"(acc) : "l"(a), "l"(w));
}
__device__ __forceinline__ float sum2(u64 v) {
    return __uint_as_float((unsigned int)v) + __uint_as_float((unsigned int)(v >> 32));
}
__device__ __forceinline__ u64 dup32(unsigned int a) {
    u64 d;
    asm("mov.b64 %0, {%1, %1};" : "=l"(d) : "r"(a));
    return d;
}

// ---------------- activations ----------------
__device__ __forceinline__ float softplus_f(float x) {
    float r = __logf(1.f + __expf(x));
    return (x > 15.f) ? x : r;
}
__device__ __forceinline__ float tanh_f(float x) {
    float xx = fminf(fmaxf(x, -12.f), 12.f);
    float e = __expf(2.f * xx);
    return (e - 1.f) * __fdividef(1.f, e + 1.f);
}

// ---------------- weight layouts ----------------
// vw3 pair-packed: for col-pair p (cols 2p,2p+1), k = kq*4 + k2*2 + ke:
//   g_w3p[(kq*2+k2)*1024 + p*4 + 2*ke + b] = vw3[(2p+b)*128 + k]
// 16B granule per (kq,k2,p) = [wA_ke0, wB_ke0, wA_ke1, wB_ke1].
__device__ float g_w3p[512 * 128];
// k-major quad-interleaved for dense layers: dst[(k>>2)*C*4 + c*4 + (k&3)]
__device__ float g_vw1k[128 * 64];
__device__ float g_vw2k[128 * 128];
__device__ float g_iw1k[128 * 8];
__device__ float g_iw2k[128 * 128];
__device__ float g_iw3k[64 * 128];

__global__ void prep_all(const float* __restrict__ vw3, const float* __restrict__ vw1,
                         const float* __restrict__ vw2, const float* __restrict__ iw1,
                         const float* __restrict__ iw2, const float* __restrict__ iw3) {
    int id = blockIdx.x * blockDim.x + threadIdx.x;
    if (id < 65536) {                              // vw3 pair-packed
        int c = id / 128, k = id % 128;
        int kq = k >> 2, k2 = (k >> 1) & 1, ke = k & 1;
        int p = c >> 1, b = c & 1;
        g_w3p[(kq * 2 + k2) * 1024 + p * 4 + 2 * ke + b] = vw3[id];
        return;
    }
    id -= 65536;
    if (id < 8192) {                               // vw1: C=128,K=64
        int c = id / 64, k = id % 64;
        g_vw1k[(k >> 2) * 512 + c * 4 + (k & 3)] = vw1[id];
        return;
    }
    id -= 8192;
    if (id < 16384) {                              // vw2: C=128,K=128
        int c = id / 128, k = id % 128;
        g_vw2k[(k >> 2) * 512 + c * 4 + (k & 3)] = vw2[id];
        return;
    }
    id -= 16384;
    if (id < 1024) {                               // iw1: C=128,K=8
        int c = id / 8, k = id % 8;
        g_iw1k[(k >> 2) * 512 + c * 4 + (k & 3)] = iw1[id];
        return;
    }
    id -= 1024;
    if (id < 16384) {                              // iw2: C=128,K=128
        int c = id / 128, k = id % 128;
        g_iw2k[(k >> 2) * 512 + c * 4 + (k & 3)] = iw2[id];
        return;
    }
    id -= 16384;
    if (id < 8192) {                               // iw3: C=64,K=128
        int c = id / 128, k = id % 128;
        g_iw3k[(k >> 2) * 256 + c * 4 + (k & 3)] = iw3[id];
        return;
    }
}

// ---------------- smem layout (floats) ----------------
#define OFF_W3C 0          // vw3 colpairs 128..255 (cols 256..511): 64 kq2 x 128 p x 4 = 32768
#define OFF_B1  32768      // 128
#define OFF_B2  32896      // 128
#define OFF_B3  33024      // 512
#define OFF_LW  33536      // 64
#define OFF_DX  33600      // 64
#define OFF_Y   33664      // 512
#define OFF_YT  34176      // 512
#define OFF_H1  34688      // 8 x 128
#define OFF_H2  35712      // 8 x 128
#define OFF_K   36736      // 6 x 512
#define OFF_SC  39808      // scratch 16384 (4 planes of 4096)
#define SMEM_FLOATS 56192
#define SMEM_BYTES (SMEM_FLOATS * 4)

enum { ACT_ID = 0, ACT_RELU = 1, ACT_SP = 2 };

// Generic split-K (S=2) dense for init path only; gmem k-major weights.
template<int C, int K, int ACT>
__device__ __forceinline__ void dense_sk(const float* __restrict__ wk,
                                         const float* __restrict__ bias,
                                         const float* __restrict__ actbuf,
                                         float* __restrict__ scratch,
                                         float* __restrict__ outp, int tid) {
    const int half = tid >> 8;
    const int t2 = tid & 255;
    constexpr int G = 256 / C;
    constexpr int RPT = 8 / G;
    constexpr int KQH = K / 8;
    const int c  = t2 % C;
    const int r0 = (t2 / C) * RPT;
    const int kq0 = half * KQH;

    u64 acc[RPT][2];
#pragma unroll
    for (int i = 0; i < RPT; i++) { acc[i][0] = 0ull; acc[i][1] = 0ull; }

#pragma unroll
    for (int q = 0; q < KQH; q++) {
        const int kq = kq0 + q;
        ulonglong2 w = *(const ulonglong2*)(wk + kq * C * 4 + c * 4);
#pragma unroll
        for (int i = 0; i < RPT; i++) {
            ulonglong2 a = *(const ulonglong2*)(actbuf + (r0 + i) * K + kq * 4);
            ffma2(acc[i][0], a.x, w.x);
            ffma2(acc[i][1], a.y, w.y);
        }
    }
#pragma unroll
    for (int i = 0; i < RPT; i++)
        scratch[half * (8 * C) + (r0 + i) * C + c] = sum2(acc[i][0]) + sum2(acc[i][1]);
    __syncthreads();

#pragma unroll
    for (int i = tid; i < 8 * C; i += NT) {
        float v = scratch[i] + scratch[8 * C + i] + bias[i % C];
        if (ACT == ACT_RELU) v = fmaxf(v, 0.f);
        if (ACT == ACT_SP)   v = softplus_f(v);
        outp[i] = v;
    }
}

// L1 recurrent: C=128, K=64, S=4 k-split, register weights (4 u64 quads).
__device__ __forceinline__ void dense1_reg(const ulonglong2* __restrict__ w1r,
                                           const float* __restrict__ bias,
                                           const float* __restrict__ ysrc,
                                           float* __restrict__ scratch,
                                           float* __restrict__ outp, int tid) {
    const int g = tid >> 7;
    const int c = tid & 127;
    u64 acc[8];
#pragma unroll
    for (int r = 0; r < 8; r++) acc[r] = 0ull;
#pragma unroll
    for (int q = 0; q < 4; q++) {
        ulonglong2 w = w1r[q];
        const int k4 = (g * 4 + q) * 4;
#pragma unroll
        for (int r = 0; r < 8; r++) {
            ulonglong2 a = *(const ulonglong2*)(ysrc + r * 64 + k4);
            ffma2(acc[r], a.x, w.x);
            ffma2(acc[r], a.y, w.y);
        }
    }
#pragma unroll
    for (int r = 0; r < 8; r++)
        scratch[g * 1024 + r * 128 + c] = sum2(acc[r]);
    __syncthreads();
#pragma unroll
    for (int i = tid; i < 1024; i += NT) {
        float v = scratch[i] + scratch[1024 + i] + scratch[2048 + i] + scratch[3072 + i]
                + bias[i & 127];
        outp[i] = softplus_f(v);
    }
}

// L2 recurrent: C=128, K=128, S=4 k-split, register weights (8 u64 quads).
__device__ __forceinline__ void dense2_reg(const ulonglong2* __restrict__ w2r,
                                           const float* __restrict__ bias,
                                           const float* __restrict__ h1,
                                           float* __restrict__ scratch,
                                           float* __restrict__ outp, int tid) {
    const int g = tid >> 7;
    const int c = tid & 127;
    u64 acc[8];
#pragma unroll
    for (int r = 0; r < 8; r++) acc[r] = 0ull;
#pragma unroll
    for (int q = 0; q < 8; q++) {
        ulonglong2 w = w2r[q];
        const int k4 = (g * 8 + q) * 4;
#pragma unroll
        for (int r = 0; r < 8; r++) {
            ulonglong2 a = *(const ulonglong2*)(h1 + r * 128 + k4);
            ffma2(acc[r], a.x, w.x);
            ffma2(acc[r], a.y, w.y);
        }
    }
#pragma unroll
    for (int r = 0; r < 8; r++)
        scratch[g * 1024 + r * 128 + c] = sum2(acc[r]);
    __syncthreads();
#pragma unroll
    for (int i = tid; i < 1024; i += NT) {
        float v = scratch[i] + scratch[1024 + i] + scratch[2048 + i] + scratch[3072 + i]
                + bias[i & 127];
        outp[i] = softplus_f(v);
    }
}

// L3 col-pair S=4: thread (g = tid>>7, t2 = tid&127) owns col-pairs t2 (gmem
// stream) and t2+128 (smem cache) over kq range [g*8, g*8+8). acc lanes =
// the two columns of a pair; acts dup'd into both lanes (1 MOV each).
// Act broadcasts halve vs S=2 (8 kq x 8 rows per thread).
__device__ __forceinline__ void l3_cp(const float* __restrict__ h2s,
                                      const float* __restrict__ w3c,
                                      const float* __restrict__ b3s,
                                      const float* __restrict__ dxs,
                                      float* __restrict__ scratch,
                                      float* __restrict__ kout, int tid) {
    const int g = tid >> 7;
    const int t2 = tid & 127;
    const int kq0 = g * 8;

    u64 acc0[8], acc1[8];
#pragma unroll
    for (int r = 0; r < 8; r++) { acc0[r] = 0ull; acc1[r] = 0ull; }

    const float* gb = g_w3p + kq0 * 2048 + t2 * 4;      // (kq*2+k2)*1024 stride
    const float* cb = w3c + kq0 * 1024 + t2 * 4;        // cache: (kq*2+k2)*512 stride

    // depth-2 prefetch on the gmem stream (2 granules per kq)
    ulonglong2 pA0 = *(const ulonglong2*)(gb);
    ulonglong2 pA1 = *(const ulonglong2*)(gb + 1024);
    ulonglong2 pB0 = *(const ulonglong2*)(gb + 2048);
    ulonglong2 pB1 = *(const ulonglong2*)(gb + 2048 + 1024);

#pragma unroll
    for (int q = 0; q < 8; q++) {
        ulonglong2 wg0 = pA0, wg1 = pA1;
        pA0 = pB0; pA1 = pB1;
        if (q + 2 < 8) {
            pB0 = *(const ulonglong2*)(gb + (q + 2) * 2048);
            pB1 = *(const ulonglong2*)(gb + (q + 2) * 2048 + 1024);
        }
        ulonglong2 ws0 = *(const ulonglong2*)(cb + q * 1024);
        ulonglong2 ws1 = *(const ulonglong2*)(cb + q * 1024 + 512);
        const int k4 = (kq0 + q) * 4;
#pragma unroll
        for (int r = 0; r < 8; r++) {
            uint4 av = *(const uint4*)(h2s + r * 128 + k4);
            u64 d0 = dup32(av.x), d1 = dup32(av.y);
            u64 d2 = dup32(av.z), d3 = dup32(av.w);
            ffma2(acc0[r], d0, wg0.x);
            ffma2(acc0[r], d1, wg0.y);
            ffma2(acc0[r], d2, wg1.x);
            ffma2(acc0[r], d3, wg1.y);
            ffma2(acc1[r], d0, ws0.x);
            ffma2(acc1[r], d1, ws0.y);
            ffma2(acc1[r], d2, ws1.x);
            ffma2(acc1[r], d3, ws1.y);
        }
    }
    // partial planes: plane g, cols (2*t2, 2*t2+1) and (2*t2+256, 2*t2+257)
#pragma unroll
    for (int r = 0; r < 8; r++) {
        *(u64*)(scratch + g * 4096 + r * 512 + 2 * t2)       = acc0[r];
        *(u64*)(scratch + g * 4096 + r * 512 + 2 * t2 + 256) = acc1[r];
    }
    __syncthreads();

    const int d  = tid & 7;
    const int h0 = tid >> 3;
    const float b3v = b3s[tid];
#pragma unroll
    for (int r = 0; r < 8; r++) {
        float v = scratch[r * 512 + tid] + scratch[4096 + r * 512 + tid]
                + scratch[8192 + r * 512 + tid] + scratch[12288 + r * 512 + tid] + b3v;
        float f = tanh_f(v) * dxs[r * 8 + d];
        f += __shfl_xor_sync(0xffffffffu, f, 1);
        f += __shfl_xor_sync(0xffffffffu, f, 2);
        f += __shfl_xor_sync(0xffffffffu, f, 4);
        if (d == 0) kout[r * 64 + h0] = f;
    }
}

__device__ __forceinline__ void vf(const float* __restrict__ ysrc, float* __restrict__ kout,
                                   const ulonglong2* w1r, const float* b1s,
                                   const ulonglong2* w2r, const float* b2s,
                                   const float* w3c, const float* b3s,
                                   const float* dxs,
                                   float* scratch, float* h1, float* h2, int tid) {
    dense1_reg(w1r, b1s, ysrc, scratch, h1, tid);
    __syncthreads();
    dense2_reg(w2r, b2s, h1, scratch, h2, tid);
    __syncthreads();
    l3_cp(h2, w3c, b3s, dxs, scratch, kout, tid);
    __syncthreads();
}

__device__ __forceinline__ void write_out(const float* __restrict__ y,
                                          const float* __restrict__ lws, float lbv,
                                          float* __restrict__ out, int b0, int t, int tid) {
    int w = tid >> 5, l = tid & 31;
    if (w < 8) {
        float p = y[w * 64 + l] * lws[l] + y[w * 64 + 32 + l] * lws[32 + l];
#pragma unroll
        for (int s = 16; s > 0; s >>= 1) p += __shfl_xor_sync(0xffffffffu, p, s);
        if (l == 0) {
            float z = p + lbv;
            out[(b0 + w) * 64 + t] = __fdividef(1.f, 1.f + __expf(-z));
        }
    }
}

__global__ void __launch_bounds__(NT, 1)
cde_kernel(const float* __restrict__ ts, const float* __restrict__ xs,
           const float* __restrict__ ib1, const float* __restrict__ ib2,
           const float* __restrict__ ib3,
           const float* __restrict__ vb1, const float* __restrict__ vb2,
           const float* __restrict__ vb3,
           const float* __restrict__ lw, const float* __restrict__ lb,
           float* __restrict__ out) {
    extern __shared__ float sm[];
    const int tid = threadIdx.x;
    const int b0 = blockIdx.x * BT;

    float* w3c = sm + OFF_W3C;
    float* b1s = sm + OFF_B1;
    float* b2s = sm + OFF_B2;
    float* b3s = sm + OFF_B3;
    float* lws = sm + OFF_LW;
    float* dxs = sm + OFF_DX;
    float* ybuf = sm + OFF_Y;
    float* yts = sm + OFF_YT;
    float* h1 = sm + OFF_H1;
    float* h2 = sm + OFF_H2;
    float* ksb = sm + OFF_K;
    float* scratch = sm + OFF_SC;

    // ---------- stage smem ----------
    // w3c[kq2*512 + pp*4 + j] = g_w3p[kq2*1024 + 512 + pp*4 + j]  (colpairs 128..255)
    for (int i = tid; i < 32768; i += NT) {
        int kq2 = i >> 9;
        int rem = i & 511;
        w3c[i] = g_w3p[kq2 * 1024 + 512 + rem];
    }
    for (int i = tid; i < 128; i += NT) { b1s[i] = vb1[i]; b2s[i] = vb2[i]; }
    for (int i = tid; i < 512; i += NT) b3s[i] = vb3[i];
    if (tid < 64) lws[tid] = lw[tid];
    if (tid < 64) {
        int r = tid >> 3, d = tid & 7;
        dxs[tid] = xs[(b0 + r) * 512 + d];         // X(t0)
    }
    const float lbv = lb[0];

    // ---------- register-resident vw1/vw2 slices (S=4) ----------
    ulonglong2 w1r[4], w2r[8];
    {
        const int g = tid >> 7;
        const int c = tid & 127;
#pragma unroll
        for (int q = 0; q < 4; q++)
            w1r[q] = *(const ulonglong2*)(g_vw1k + (g * 4 + q) * 512 + c * 4);
#pragma unroll
        for (int q = 0; q < 8; q++)
            w2r[q] = *(const ulonglong2*)(g_vw2k + (g * 8 + q) * 512 + c * 4);
    }
    __syncthreads();

    // ---------- initial MLP (gmem k-major weights, S=2 generic) ----------
    dense_sk<128, 8, ACT_RELU>(g_iw1k, ib1, dxs, scratch, h1, tid);
    __syncthreads();
    dense_sk<128, 128, ACT_RELU>(g_iw2k, ib2, h1, scratch, h2, tid);
    __syncthreads();
    dense_sk<64, 128, ACT_ID>(g_iw3k, ib3, h2, scratch, ybuf, tid);
    __syncthreads();

    write_out(ybuf, lws, lbv, out, b0, 0, tid);
    __syncthreads();

    // Tsit5 coefficients
    const float A21 = 0.161f;
    const float A31 = -0.008480655492356989f, A32 = 0.335480655492357f;
    const float A41 = 2.8971530571054935f, A42 = -6.359448489975075f, A43 = 4.3622954328695815f;
    const float A51 = 5.325864828439257f, A52 = -11.748883564062828f, A53 = 7.4955393428898365f, A54 = -0.09249506636175525f;
    const float A61 = 5.86145544294642f, A62 = -12.92096931784711f, A63 = 8.159367898576159f, A64 = -0.071584973281401f, A65 = -0.028269050394068383f;
    const float B1 = 0.09646076681806523f, B2 = 0.01f, B3 = 0.4798896504144996f;
    const float B4 = 1.379008574103742f, B5 = -3.290069515436081f, B6 = 2.324710524099774f;

    float* k1 = ksb;
    float* k2 = ksb + 512;
    float* k3 = ksb + 1024;
    float* k4 = ksb + 1536;
    float* k5 = ksb + 2048;
    float* k6 = ksb + 2560;

    for (int t = 0; t < 63; t++) {
        const float dt = ts[t + 1] - ts[t];
        if (tid < 64) {
            int r = tid >> 3, d = tid & 7;
            int ix = (b0 + r) * 512 + t * 8 + d;
            dxs[tid] = (xs[ix + 8] - xs[ix]) / dt;
        }
        __syncthreads();

        vf(ybuf, k1, w1r, b1s, w2r, b2s, w3c, b3s, dxs, scratch, h1, h2, tid);
        yts[tid] = ybuf[tid] + dt * (A21 * k1[tid]);
        __syncthreads();

        vf(yts, k2, w1r, b1s, w2r, b2s, w3c, b3s, dxs, scratch, h1, h2, tid);
        yts[tid] = ybuf[tid] + dt * (A31 * k1[tid] + A32 * k2[tid]);
        __syncthreads();

        vf(yts, k3, w1r, b1s, w2r, b2s, w3c, b3s, dxs, scratch, h1, h2, tid);
        yts[tid] = ybuf[tid] + dt * (A41 * k1[tid] + A42 * k2[tid] + A43 * k3[tid]);
        __syncthreads();

        vf(yts, k4, w1r, b1s, w2r, b2s, w3c, b3s, dxs, scratch, h1, h2, tid);
        yts[tid] = ybuf[tid] + dt * (A51 * k1[tid] + A52 * k2[tid] + A53 * k3[tid] + A54 * k4[tid]);
        __syncthreads();

        vf(yts, k5, w1r, b1s, w2r, b2s, w3c, b3s, dxs, scratch, h1, h2, tid);
        yts[tid] = ybuf[tid] + dt * (A61 * k1[tid] + A62 * k2[tid] + A63 * k3[tid] + A64 * k4[tid] + A65 * k5[tid]);
        __syncthreads();

        vf(yts, k6, w1r, b1s, w2r, b2s, w3c, b3s, dxs, scratch, h1, h2, tid);
        ybuf[tid] = ybuf[tid] + dt * (B1 * k1[tid] + B2 * k2[tid] + B3 * k3[tid]
                                    + B4 * k4[tid] + B5 * k5[tid] + B6 * k6[tid]);
        __syncthreads();

        write_out(ybuf, lws, lbv, out, b0, t + 1, tid);
        __syncthreads();
    }
}

extern "C" void kernel_launch(void* const* d_in, const int* in_sizes, int n_in,
                              void* d_out, int out_size) {
    const float* ts  = (const float*)d_in[0];
    const float* xs  = (const float*)d_in[1];
    const float* iw1 = (const float*)d_in[2];
    const float* ib1 = (const float*)d_in[3];
    const float* iw2 = (const float*)d_in[4];
    const float* ib2 = (const float*)d_in[5];
    const float* iw3 = (const float*)d_in[6];
    const float* ib3 = (const float*)d_in[7];
    const float* vw1 = (const float*)d_in[8];
    const float* vb1 = (const float*)d_in[9];
    const float* vw2 = (const float*)d_in[10];
    const float* vb2 = (const float*)d_in[11];
    const float* vw3 = (const float*)d_in[12];
    const float* vb3 = (const float*)d_in[13];
    const float* lw  = (const float*)d_in[14];
    const float* lb  = (const float*)d_in[15];
    float* out = (float*)d_out;

    prep_all<<<(115712 + 255) / 256, 256>>>(vw3, vw1, vw2, iw1, iw2, iw3);

    cudaFuncSetAttribute(cde_kernel, cudaFuncAttributeMaxDynamicSharedMemorySize, SMEM_BYTES);
    cde_kernel<<<128, NT, SMEM_BYTES>>>(ts, xs, ib1, ib2, ib3,
                                        vb1, vb2, vb3, lw, lb, out);
}

// round 17
// speedup vs baseline: 1.4593x; 1.0348x over previous
#include <cuda_runtime.h>

#define NT 512
#define BT 8

typedef unsigned long long u64;

// ---------------- packed f32x2 helpers ----------------
__device__ __forceinline__ void ffma2(u64 &acc, u64 a, u64 w) {
    asm("fma.rn.f32x2 %0, %1, %2, %0;" : "+l"(acc) : "l"(a), "l"(w));
}
__device__ __forceinline__ float sum2(u64 v) {
    return __uint_as_float((unsigned int)v) + __uint_as_float((unsigned int)(v >> 32));
}
__device__ __forceinline__ u64 dup32(unsigned int a) {
    u64 d;
    asm("mov.b64 %0, {%1, %1};" : "=l"(d) : "r"(a));
    return d;
}

// ---------------- activations ----------------
__device__ __forceinline__ float softplus_f(float x) {
    float r = __logf(1.f + __expf(x));
    return (x > 15.f) ? x : r;
}
__device__ __forceinline__ float tanh_f(float x) {
    float xx = fminf(fmaxf(x, -12.f), 12.f);
    float e = __expf(2.f * xx);
    return (e - 1.f) * __fdividef(1.f, e + 1.f);
}

// ---------------- weight layouts ----------------
// Pair-packed (for col-pair f32x2 lanes): col-pair p = cols (2p, 2p+1),
// k = kq*4 + k2*2 + ke:
//   dst[(kq*2+k2)*NP*4 + p*4 + 2*ke + b] = src[(2p+b)*K + k],  NP = C/2
__device__ float g_w3p[512 * 128];    // NP=256
__device__ float g_w1p[128 * 64];     // NP=64, K=64
__device__ float g_w2p[128 * 128];    // NP=64, K=128
// k-major quad-interleaved (init path): dst[(k>>2)*C*4 + c*4 + (k&3)]
__device__ float g_iw1k[128 * 8];
__device__ float g_iw2k[128 * 128];
__device__ float g_iw3k[64 * 128];

__global__ void prep_all(const float* __restrict__ vw3, const float* __restrict__ vw1,
                         const float* __restrict__ vw2, const float* __restrict__ iw1,
                         const float* __restrict__ iw2, const float* __restrict__ iw3) {
    int id = blockIdx.x * blockDim.x + threadIdx.x;
    if (id < 65536) {                              // vw3 pair-packed (NP=256)
        int c = id / 128, k = id % 128;
        int kq = k >> 2, k2 = (k >> 1) & 1, ke = k & 1;
        int p = c >> 1, b = c & 1;
        g_w3p[(kq * 2 + k2) * 1024 + p * 4 + 2 * ke + b] = vw3[id];
        return;
    }
    id -= 65536;
    if (id < 8192) {                               // vw1 pair-packed (NP=64, K=64)
        int c = id / 64, k = id % 64;
        int kq = k >> 2, k2 = (k >> 1) & 1, ke = k & 1;
        int p = c >> 1, b = c & 1;
        g_w1p[(kq * 2 + k2) * 256 + p * 4 + 2 * ke + b] = vw1[id];
        return;
    }
    id -= 8192;
    if (id < 16384) {                              // vw2 pair-packed (NP=64, K=128)
        int c = id / 128, k = id % 128;
        int kq = k >> 2, k2 = (k >> 1) & 1, ke = k & 1;
        int p = c >> 1, b = c & 1;
        g_w2p[(kq * 2 + k2) * 256 + p * 4 + 2 * ke + b] = vw2[id];
        return;
    }
    id -= 16384;
    if (id < 1024) {                               // iw1: C=128,K=8
        int c = id / 8, k = id % 8;
        g_iw1k[(k >> 2) * 512 + c * 4 + (k & 3)] = iw1[id];
        return;
    }
    id -= 1024;
    if (id < 16384) {                              // iw2: C=128,K=128
        int c = id / 128, k = id % 128;
        g_iw2k[(k >> 2) * 512 + c * 4 + (k & 3)] = iw2[id];
        return;
    }
    id -= 16384;
    if (id < 8192) {                               // iw3: C=64,K=128
        int c = id / 128, k = id % 128;
        g_iw3k[(k >> 2) * 256 + c * 4 + (k & 3)] = iw3[id];
        return;
    }
}

// ---------------- smem layout (floats) ----------------
#define OFF_W3C 0          // vw3 colpairs 128..255 (cols 256..511): 32768
#define OFF_B1  32768      // 128
#define OFF_B2  32896      // 128
#define OFF_B3  33024      // 512
#define OFF_LW  33536      // 64
#define OFF_DX  33600      // 64
#define OFF_Y   33664      // 512
#define OFF_YT  34176      // 512
#define OFF_H1  34688      // 8 x 128
#define OFF_H2  35712      // 8 x 128
#define OFF_K   36736      // 6 x 512
#define OFF_SC  39808      // scratch 16384 (l3: 4 planes x 4096; dense: 8 planes x 1024)
#define SMEM_FLOATS 56192
#define SMEM_BYTES (SMEM_FLOATS * 4)

enum { ACT_ID = 0, ACT_RELU = 1, ACT_SP = 2 };

// Generic split-K (S=2) dense for init path only; gmem k-major weights.
template<int C, int K, int ACT>
__device__ __forceinline__ void dense_sk(const float* __restrict__ wk,
                                         const float* __restrict__ bias,
                                         const float* __restrict__ actbuf,
                                         float* __restrict__ scratch,
                                         float* __restrict__ outp, int tid) {
    const int half = tid >> 8;
    const int t2 = tid & 255;
    constexpr int G = 256 / C;
    constexpr int RPT = 8 / G;
    constexpr int KQH = K / 8;
    const int c  = t2 % C;
    const int r0 = (t2 / C) * RPT;
    const int kq0 = half * KQH;

    u64 acc[RPT][2];
#pragma unroll
    for (int i = 0; i < RPT; i++) { acc[i][0] = 0ull; acc[i][1] = 0ull; }

#pragma unroll
    for (int q = 0; q < KQH; q++) {
        const int kq = kq0 + q;
        ulonglong2 w = *(const ulonglong2*)(wk + kq * C * 4 + c * 4);
#pragma unroll
        for (int i = 0; i < RPT; i++) {
            ulonglong2 a = *(const ulonglong2*)(actbuf + (r0 + i) * K + kq * 4);
            ffma2(acc[i][0], a.x, w.x);
            ffma2(acc[i][1], a.y, w.y);
        }
    }
#pragma unroll
    for (int i = 0; i < RPT; i++)
        scratch[half * (8 * C) + (r0 + i) * C + c] = sum2(acc[i][0]) + sum2(acc[i][1]);
    __syncthreads();

#pragma unroll
    for (int i = tid; i < 8 * C; i += NT) {
        float v = scratch[i] + scratch[8 * C + i] + bias[i % C];
        if (ACT == ACT_RELU) v = fmaxf(v, 0.f);
        if (ACT == ACT_SP)   v = softplus_f(v);
        outp[i] = v;
    }
}

// L1 recurrent: C=128, K=64, col-pair S=8. thread: p = tid&63, g = tid>>6.
// Covers kq in [g*2, g*2+2), cols (2p, 2p+1) as f32x2 lanes. Register
// weights w1r[4] (2 kq x 2 granules). Acts dup'd into both lanes.
__device__ __forceinline__ void dense1_reg(const ulonglong2* __restrict__ w1r,
                                           const float* __restrict__ bias,
                                           const float* __restrict__ ysrc,
                                           float* __restrict__ scratch,
                                           float* __restrict__ outp, int tid) {
    const int g = tid >> 6;
    const int p = tid & 63;
    u64 acc[8];
#pragma unroll
    for (int r = 0; r < 8; r++) acc[r] = 0ull;
#pragma unroll
    for (int qi = 0; qi < 2; qi++) {
        const int kq = g * 2 + qi;
        ulonglong2 wa = w1r[2 * qi];
        ulonglong2 wb = w1r[2 * qi + 1];
#pragma unroll
        for (int r = 0; r < 8; r++) {
            uint4 av = *(const uint4*)(ysrc + r * 64 + kq * 4);
            ffma2(acc[r], dup32(av.x), wa.x);
            ffma2(acc[r], dup32(av.y), wa.y);
            ffma2(acc[r], dup32(av.z), wb.x);
            ffma2(acc[r], dup32(av.w), wb.y);
        }
    }
#pragma unroll
    for (int r = 0; r < 8; r++)
        *(u64*)(scratch + g * 1024 + r * 128 + 2 * p) = acc[r];
    __syncthreads();
#pragma unroll
    for (int i = tid; i < 1024; i += NT) {
        float v = bias[i & 127];
#pragma unroll
        for (int gg = 0; gg < 8; gg++) v += scratch[gg * 1024 + i];
        outp[i] = softplus_f(v);
    }
}

// L2 recurrent: C=128, K=128, col-pair S=8. thread: p = tid&63, g = tid>>6.
// Covers kq in [g*4, g*4+4). Register weights w2r[8] (4 kq x 2 granules).
__device__ __forceinline__ void dense2_reg(const ulonglong2* __restrict__ w2r,
                                           const float* __restrict__ bias,
                                           const float* __restrict__ h1,
                                           float* __restrict__ scratch,
                                           float* __restrict__ outp, int tid) {
    const int g = tid >> 6;
    const int p = tid & 63;
    u64 acc[8];
#pragma unroll
    for (int r = 0; r < 8; r++) acc[r] = 0ull;
#pragma unroll
    for (int qi = 0; qi < 4; qi++) {
        const int kq = g * 4 + qi;
        ulonglong2 wa = w2r[2 * qi];
        ulonglong2 wb = w2r[2 * qi + 1];
#pragma unroll
        for (int r = 0; r < 8; r++) {
            uint4 av = *(const uint4*)(h1 + r * 128 + kq * 4);
            ffma2(acc[r], dup32(av.x), wa.x);
            ffma2(acc[r], dup32(av.y), wa.y);
            ffma2(acc[r], dup32(av.z), wb.x);
            ffma2(acc[r], dup32(av.w), wb.y);
        }
    }
#pragma unroll
    for (int r = 0; r < 8; r++)
        *(u64*)(scratch + g * 1024 + r * 128 + 2 * p) = acc[r];
    __syncthreads();
#pragma unroll
    for (int i = tid; i < 1024; i += NT) {
        float v = bias[i & 127];
#pragma unroll
        for (int gg = 0; gg < 8; gg++) v += scratch[gg * 1024 + i];
        outp[i] = softplus_f(v);
    }
}

// L3 col-pair S=4 (unchanged from R16): thread (g = tid>>7, t2 = tid&127)
// owns col-pairs t2 (gmem stream) and t2+128 (smem cache) over kq [g*8, g*8+8).
__device__ __forceinline__ void l3_cp(const float* __restrict__ h2s,
                                      const float* __restrict__ w3c,
                                      const float* __restrict__ b3s,
                                      const float* __restrict__ dxs,
                                      float* __restrict__ scratch,
                                      float* __restrict__ kout, int tid) {
    const int g = tid >> 7;
    const int t2 = tid & 127;
    const int kq0 = g * 8;

    u64 acc0[8], acc1[8];
#pragma unroll
    for (int r = 0; r < 8; r++) { acc0[r] = 0ull; acc1[r] = 0ull; }

    const float* gb = g_w3p + kq0 * 2048 + t2 * 4;
    const float* cb = w3c + kq0 * 1024 + t2 * 4;

    ulonglong2 pA0 = *(const ulonglong2*)(gb);
    ulonglong2 pA1 = *(const ulonglong2*)(gb + 1024);
    ulonglong2 pB0 = *(const ulonglong2*)(gb + 2048);
    ulonglong2 pB1 = *(const ulonglong2*)(gb + 2048 + 1024);

#pragma unroll
    for (int q = 0; q < 8; q++) {
        ulonglong2 wg0 = pA0, wg1 = pA1;
        pA0 = pB0; pA1 = pB1;
        if (q + 2 < 8) {
            pB0 = *(const ulonglong2*)(gb + (q + 2) * 2048);
            pB1 = *(const ulonglong2*)(gb + (q + 2) * 2048 + 1024);
        }
        ulonglong2 ws0 = *(const ulonglong2*)(cb + q * 1024);
        ulonglong2 ws1 = *(const ulonglong2*)(cb + q * 1024 + 512);
        const int k4 = (kq0 + q) * 4;
#pragma unroll
        for (int r = 0; r < 8; r++) {
            uint4 av = *(const uint4*)(h2s + r * 128 + k4);
            u64 d0 = dup32(av.x), d1 = dup32(av.y);
            u64 d2 = dup32(av.z), d3 = dup32(av.w);
            ffma2(acc0[r], d0, wg0.x);
            ffma2(acc0[r], d1, wg0.y);
            ffma2(acc0[r], d2, wg1.x);
            ffma2(acc0[r], d3, wg1.y);
            ffma2(acc1[r], d0, ws0.x);
            ffma2(acc1[r], d1, ws0.y);
            ffma2(acc1[r], d2, ws1.x);
            ffma2(acc1[r], d3, ws1.y);
        }
    }
#pragma unroll
    for (int r = 0; r < 8; r++) {
        *(u64*)(scratch + g * 4096 + r * 512 + 2 * t2)       = acc0[r];
        *(u64*)(scratch + g * 4096 + r * 512 + 2 * t2 + 256) = acc1[r];
    }
    __syncthreads();

    const int d  = tid & 7;
    const int h0 = tid >> 3;
    const float b3v = b3s[tid];
#pragma unroll
    for (int r = 0; r < 8; r++) {
        float v = scratch[r * 512 + tid] + scratch[4096 + r * 512 + tid]
                + scratch[8192 + r * 512 + tid] + scratch[12288 + r * 512 + tid] + b3v;
        float f = tanh_f(v) * dxs[r * 8 + d];
        f += __shfl_xor_sync(0xffffffffu, f, 1);
        f += __shfl_xor_sync(0xffffffffu, f, 2);
        f += __shfl_xor_sync(0xffffffffu, f, 4);
        if (d == 0) kout[r * 64 + h0] = f;
    }
}

__device__ __forceinline__ void vf(const float* __restrict__ ysrc, float* __restrict__ kout,
                                   const ulonglong2* w1r, const float* b1s,
                                   const ulonglong2* w2r, const float* b2s,
                                   const float* w3c, const float* b3s,
                                   const float* dxs,
                                   float* scratch, float* h1, float* h2, int tid) {
    dense1_reg(w1r, b1s, ysrc, scratch, h1, tid);
    __syncthreads();
    dense2_reg(w2r, b2s, h1, scratch, h2, tid);
    __syncthreads();
    l3_cp(h2, w3c, b3s, dxs, scratch, kout, tid);
    __syncthreads();
}

__device__ __forceinline__ void write_out(const float* __restrict__ y,
                                          const float* __restrict__ lws, float lbv,
                                          float* __restrict__ out, int b0, int t, int tid) {
    int w = tid >> 5, l = tid & 31;
    if (w < 8) {
        float p = y[w * 64 + l] * lws[l] + y[w * 64 + 32 + l] * lws[32 + l];
#pragma unroll
        for (int s = 16; s > 0; s >>= 1) p += __shfl_xor_sync(0xffffffffu, p, s);
        if (l == 0) {
            float z = p + lbv;
            out[(b0 + w) * 64 + t] = __fdividef(1.f, 1.f + __expf(-z));
        }
    }
}

__global__ void __launch_bounds__(NT, 1)
cde_kernel(const float* __restrict__ ts, const float* __restrict__ xs,
           const float* __restrict__ ib1, const float* __restrict__ ib2,
           const float* __restrict__ ib3,
           const float* __restrict__ vb1, const float* __restrict__ vb2,
           const float* __restrict__ vb3,
           const float* __restrict__ lw, const float* __restrict__ lb,
           float* __restrict__ out) {
    extern __shared__ float sm[];
    const int tid = threadIdx.x;
    const int b0 = blockIdx.x * BT;

    float* w3c = sm + OFF_W3C;
    float* b1s = sm + OFF_B1;
    float* b2s = sm + OFF_B2;
    float* b3s = sm + OFF_B3;
    float* lws = sm + OFF_LW;
    float* dxs = sm + OFF_DX;
    float* ybuf = sm + OFF_Y;
    float* yts = sm + OFF_YT;
    float* h1 = sm + OFF_H1;
    float* h2 = sm + OFF_H2;
    float* ksb = sm + OFF_K;
    float* scratch = sm + OFF_SC;

    // ---------- stage smem ----------
    for (int i = tid; i < 32768; i += NT) {
        int kq2 = i >> 9;
        int rem = i & 511;
        w3c[i] = g_w3p[kq2 * 1024 + 512 + rem];
    }
    for (int i = tid; i < 128; i += NT) { b1s[i] = vb1[i]; b2s[i] = vb2[i]; }
    for (int i = tid; i < 512; i += NT) b3s[i] = vb3[i];
    if (tid < 64) lws[tid] = lw[tid];
    if (tid < 64) {
        int r = tid >> 3, d = tid & 7;
        dxs[tid] = xs[(b0 + r) * 512 + d];         // X(t0) for init MLP
    }
    const float lbv = lb[0];

    // ---------- register-resident vw1/vw2 pair-packed slices (S=8) ----------
    ulonglong2 w1r[4], w2r[8];
    {
        const int g = tid >> 6;
        const int p = tid & 63;
#pragma unroll
        for (int j = 0; j < 4; j++) {
            int kq = g * 2 + (j >> 1), k2 = j & 1;
            w1r[j] = *(const ulonglong2*)(g_w1p + (kq * 2 + k2) * 256 + p * 4);
        }
#pragma unroll
        for (int j = 0; j < 8; j++) {
            int kq = g * 4 + (j >> 1), k2 = j & 1;
            w2r[j] = *(const ulonglong2*)(g_w2p + (kq * 2 + k2) * 256 + p * 4);
        }
    }
    __syncthreads();

    // ---------- initial MLP (gmem k-major weights, S=2 generic) ----------
    dense_sk<128, 8, ACT_RELU>(g_iw1k, ib1, dxs, scratch, h1, tid);
    __syncthreads();
    dense_sk<128, 128, ACT_RELU>(g_iw2k, ib2, h1, scratch, h2, tid);
    __syncthreads();
    dense_sk<64, 128, ACT_ID>(g_iw3k, ib3, h2, scratch, ybuf, tid);
    __syncthreads();

    // write t=0 output + dx for step 0 (no trailing sync: dense1's internal
    // barrier inside stage 1 orders dxs before any l3 read).
    write_out(ybuf, lws, lbv, out, b0, 0, tid);
    {
        float dt0 = ts[1] - ts[0];
        if (tid < 64) {
            int r = tid >> 3, d = tid & 7;
            int ix = (b0 + r) * 512 + d;
            dxs[tid] = (xs[ix + 8] - xs[ix]) / dt0;
        }
    }
    __syncthreads();

    // Tsit5 coefficients
    const float A21 = 0.161f;
    const float A31 = -0.008480655492356989f, A32 = 0.335480655492357f;
    const float A41 = 2.8971530571054935f, A42 = -6.359448489975075f, A43 = 4.3622954328695815f;
    const float A51 = 5.325864828439257f, A52 = -11.748883564062828f, A53 = 7.4955393428898365f, A54 = -0.09249506636175525f;
    const float A61 = 5.86145544294642f, A62 = -12.92096931784711f, A63 = 8.159367898576159f, A64 = -0.071584973281401f, A65 = -0.028269050394068383f;
    const float B1 = 0.09646076681806523f, B2 = 0.01f, B3 = 0.4798896504144996f;
    const float B4 = 1.379008574103742f, B5 = -3.290069515436081f, B6 = 2.324710524099774f;

    float* k1 = ksb;
    float* k2 = ksb + 512;
    float* k3 = ksb + 1024;
    float* k4 = ksb + 1536;
    float* k5 = ksb + 2048;
    float* k6 = ksb + 2560;

    for (int t = 0; t < 63; t++) {
        const float dt = ts[t + 1] - ts[t];
        // prefetch next step's dx inputs into registers (consumed at tail)
        float xa = 0.f, xb = 0.f, dtn = 1.f;
        if (t < 62) {
            dtn = ts[t + 2] - ts[t + 1];
            if (tid < 64) {
                int r = tid >> 3, d = tid & 7;
                int ix = (b0 + r) * 512 + (t + 1) * 8 + d;
                xa = xs[ix];
                xb = xs[ix + 8];
            }
        }

        vf(ybuf, k1, w1r, b1s, w2r, b2s, w3c, b3s, dxs, scratch, h1, h2, tid);
        yts[tid] = ybuf[tid] + dt * (A21 * k1[tid]);
        __syncthreads();

        vf(yts, k2, w1r, b1s, w2r, b2s, w3c, b3s, dxs, scratch, h1, h2, tid);
        yts[tid] = ybuf[tid] + dt * (A31 * k1[tid] + A32 * k2[tid]);
        __syncthreads();

        vf(yts, k3, w1r, b1s, w2r, b2s, w3c, b3s, dxs, scratch, h1, h2, tid);
        yts[tid] = ybuf[tid] + dt * (A41 * k1[tid] + A42 * k2[tid] + A43 * k3[tid]);
        __syncthreads();

        vf(yts, k4, w1r, b1s, w2r, b2s, w3c, b3s, dxs, scratch, h1, h2, tid);
        yts[tid] = ybuf[tid] + dt * (A51 * k1[tid] + A52 * k2[tid] + A53 * k3[tid] + A54 * k4[tid]);
        __syncthreads();

        vf(yts, k5, w1r, b1s, w2r, b2s, w3c, b3s, dxs, scratch, h1, h2, tid);
        yts[tid] = ybuf[tid] + dt * (A61 * k1[tid] + A62 * k2[tid] + A63 * k3[tid] + A64 * k4[tid] + A65 * k5[tid]);
        __syncthreads();

        vf(yts, k6, w1r, b1s, w2r, b2s, w3c, b3s, dxs, scratch, h1, h2, tid);
        ybuf[tid] = ybuf[tid] + dt * (B1 * k1[tid] + B2 * k2[tid] + B3 * k3[tid]
                                    + B4 * k4[tid] + B5 * k5[tid] + B6 * k6[tid]);
        __syncthreads();

        // tail: output + next-step dxs (prefetched); no trailing sync —
        // stage-1 dense1's internal barrier orders dxs/ybuf uses, and
        // write_out/dense1 only READ ybuf.
        write_out(ybuf, lws, lbv, out, b0, t + 1, tid);
        if (t < 62 && tid < 64)
            dxs[tid] = (xb - xa) / dtn;
    }
}

extern "C" void kernel_launch(void* const* d_in, const int* in_sizes, int n_in,
                              void* d_out, int out_size) {
    const float* ts  = (const float*)d_in[0];
    const float* xs  = (const float*)d_in[1];
    const float* iw1 = (const float*)d_in[2];
    const float* ib1 = (const float*)d_in[3];
    const float* iw2 = (const float*)d_in[4];
    const float* ib2 = (const float*)d_in[5];
    const float* iw3 = (const float*)d_in[6];
    const float* ib3 = (const float*)d_in[7];
    const float* vw1 = (const float*)d_in[8];
    const float* vb1 = (const float*)d_in[9];
    const float* vw2 = (const float*)d_in[10];
    const float* vb2 = (const float*)d_in[11];
    const float* vw3 = (const float*)d_in[12];
    const float* vb3 = (const float*)d_in[13];
    const float* lw  = (const float*)d_in[14];
    const float* lb  = (const float*)d_in[15];
    float* out = (float*)d_out;

    prep_all<<<(115712 + 255) / 256, 256>>>(vw3, vw1, vw2, iw1, iw2, iw3);

    cudaFuncSetAttribute(cde_kernel, cudaFuncAttributeMaxDynamicSharedMemorySize, SMEM_BYTES);
    cde_kernel<<<128, NT, SMEM_BYTES>>>(ts, xs, ib1, ib2, ib3,
                                        vb1, vb2, vb3, lw, lb, out);
}